// round 3
// baseline (speedup 1.0000x reference)
#include <cuda.h>
#include <cuda_runtime.h>
#include <cuda_fp16.h>
#include <cstdint>

// ---------------- problem sizes ----------------
#define MM 8192
#define NN 4096
#define KK 4096
#define GRP 64

#define BM 128
#define BN 128
#define BK 128                    // bytes of K per tile (int8)
#define NSTAGE 4
#define KITER (KK / BK)           // 32
#define NGRP (KK / GRP)           // 64 groups per row

#define A_BYTES (BM * BK)         // 16384
#define B_BYTES (BN * BK)         // 16384
#define STG_BYTES (A_BYTES + B_BYTES)   // 32768

#define SM_ALPHA 0                /* 128 floats */
#define SM_BARS 512               /* NSTAGE mbarriers */
#define SM_TILE 1024
#define SMEM_TOTAL (SM_TILE + NSTAGE * STG_BYTES)   /* 132096 */

// ---------------- scratch (no allocations allowed) ----------------
__device__ __align__(1024) int8_t g_xa[(size_t)MM * KK];   // 32 MB int8 activations
__device__ __align__(1024) int8_t g_wb[(size_t)NN * KK];   // 16 MB int8 signs
__device__ float g_xs[(size_t)MM * NGRP];                  // 2 MB per-(row,group) scale = s/127
__device__ float g_alpha[NN];

// ---------------- PTX helpers (sm_90-level features only; no tcgen05) ----------------
__device__ __forceinline__ uint32_t smem_u32(const void* p) {
    uint32_t a;
    asm("{ .reg .u64 t; cvta.to.shared.u64 t, %1; cvt.u32.u64 %0, t; }" : "=r"(a) : "l"(p));
    return a;
}
__device__ __forceinline__ void mbar_init(uint32_t a, uint32_t c) {
    asm volatile("mbarrier.init.shared.b64 [%0], %1;" :: "r"(a), "r"(c) : "memory");
}
__device__ __forceinline__ void mbar_expect(uint32_t a, uint32_t bytes) {
    asm volatile("mbarrier.arrive.expect_tx.shared.b64 _, [%0], %1;" :: "r"(a), "r"(bytes) : "memory");
}
__device__ __forceinline__ void mbar_wait(uint32_t a, uint32_t p) {
    asm volatile(
        "{\n\t.reg .pred P;\n\t"
        "WL%=:\n\t"
        "mbarrier.try_wait.parity.acquire.cta.shared::cta.b64 P, [%0], %1, 0x989680;\n\t"
        "@P bra.uni WD%=;\n\t"
        "bra.uni WL%=;\n\t"
        "WD%=:\n\t}"
        :: "r"(a), "r"(p) : "memory");
}
__device__ __forceinline__ void tma_load_2d(uint32_t smem_addr, const void* map,
                                            int cx, int cy, uint32_t mbar) {
    asm volatile(
        "cp.async.bulk.tensor.2d.shared::cta.global.tile.mbarrier::complete_tx::bytes "
        "[%0], [%1, {%2, %3}], [%4];"
        :: "r"(smem_addr), "l"(map), "r"(cx), "r"(cy), "r"(mbar) : "memory");
}
__device__ __forceinline__ void ldsm_x4(uint32_t addr, uint32_t* r) {
    asm volatile("ldmatrix.sync.aligned.m8n8.x4.shared.b16 {%0,%1,%2,%3}, [%4];"
                 : "=r"(r[0]), "=r"(r[1]), "=r"(r[2]), "=r"(r[3]) : "r"(addr));
}
__device__ __forceinline__ void imma_acc(int* c, const uint32_t* a, const uint32_t* b) {
    asm volatile(
        "mma.sync.aligned.m16n8k32.row.col.s32.s8.s8.s32 "
        "{%0,%1,%2,%3}, {%4,%5,%6,%7}, {%8,%9}, {%0,%1,%2,%3};"
        : "+r"(c[0]), "+r"(c[1]), "+r"(c[2]), "+r"(c[3])
        : "r"(a[0]), "r"(a[1]), "r"(a[2]), "r"(a[3]), "r"(b[0]), "r"(b[1]));
}
__device__ __forceinline__ void imma_zero(int* d, const uint32_t* a, const uint32_t* b) {
    asm volatile(
        "mma.sync.aligned.m16n8k32.row.col.s32.s8.s8.s32 "
        "{%0,%1,%2,%3}, {%4,%5,%6,%7}, {%8,%9}, {%10,%10,%10,%10};"
        : "=r"(d[0]), "=r"(d[1]), "=r"(d[2]), "=r"(d[3])
        : "r"(a[0]), "r"(a[1]), "r"(a[2]), "r"(a[3]), "r"(b[0]), "r"(b[1]), "r"(0));
}

// ---------------- kernel 1: group-64 absmax quant of x -> int8 q + fp32 scale ----------------
__global__ void __launch_bounds__(256) quant_x_kernel(const float* __restrict__ x) {
    uint32_t t = blockIdx.x * 256u + threadIdx.x;
    size_t gi = (size_t)(t >> 4);
    size_t base = gi * GRP + (size_t)(t & 15) * 4;
    float4 v = *reinterpret_cast<const float4*>(x + base);
    float am = fmaxf(fmaxf(fabsf(v.x), fabsf(v.y)), fmaxf(fabsf(v.z), fabsf(v.w)));
    am = fmaxf(am, __shfl_xor_sync(0xFFFFFFFFu, am, 1));
    am = fmaxf(am, __shfl_xor_sync(0xFFFFFFFFu, am, 2));
    am = fmaxf(am, __shfl_xor_sync(0xFFFFFFFFu, am, 4));
    am = fmaxf(am, __shfl_xor_sync(0xFFFFFFFFu, am, 8));
    float s = fmaxf(am, 1e-8f);
    float inv = __fdividef(127.0f, s);
    int q0 = __float2int_rn(fminf(fmaxf(v.x * inv, -127.f), 127.f));
    int q1 = __float2int_rn(fminf(fmaxf(v.y * inv, -127.f), 127.f));
    int q2 = __float2int_rn(fminf(fmaxf(v.z * inv, -127.f), 127.f));
    int q3 = __float2int_rn(fminf(fmaxf(v.w * inv, -127.f), 127.f));
    uint32_t p = (uint32_t)(q0 & 255) | ((uint32_t)(q1 & 255) << 8) |
                 ((uint32_t)(q2 & 255) << 16) | ((uint32_t)(q3 & 255) << 24);
    *reinterpret_cast<uint32_t*>(g_xa + base) = p;
    if ((t & 15) == 0) g_xs[gi] = s * (1.0f / 127.0f);
}

// ---------------- kernel 2: per-row W binarize (centered sign) + alpha ----------------
__global__ void __launch_bounds__(256) quant_w_kernel(const float* __restrict__ W) {
    const int row = blockIdx.x;
    const int tid = threadIdx.x;
    const float4* wr = reinterpret_cast<const float4*>(W + (size_t)row * KK);
    float4 v[4];
    float s = 0.f;
#pragma unroll
    for (int i = 0; i < 4; i++) {
        v[i] = wr[i * 256 + tid];
        s += (v[i].x + v[i].y) + (v[i].z + v[i].w);
    }
    __shared__ float red[256];
    red[tid] = s;
    __syncthreads();
#pragma unroll
    for (int o = 128; o > 0; o >>= 1) {
        if (tid < o) red[tid] += red[tid + o];
        __syncthreads();
    }
    float mean = red[0] * (1.0f / 4096.0f);
    __syncthreads();
    float sa = 0.f;
#pragma unroll
    for (int i = 0; i < 4; i++)
        sa += (fabsf(v[i].x - mean) + fabsf(v[i].y - mean)) +
              (fabsf(v[i].z - mean) + fabsf(v[i].w - mean));
    red[tid] = sa;
    __syncthreads();
#pragma unroll
    for (int o = 128; o > 0; o >>= 1) {
        if (tid < o) red[tid] += red[tid + o];
        __syncthreads();
    }
    if (tid == 0) g_alpha[row] = red[0] * (1.0f / 4096.0f);
    int8_t* wrow = g_wb + (size_t)row * KK;
#pragma unroll
    for (int i = 0; i < 4; i++) {
        float c0 = v[i].x - mean, c1 = v[i].y - mean, c2 = v[i].z - mean, c3 = v[i].w - mean;
        int b0 = (c0 > 0.f) ? 1 : ((c0 < 0.f) ? -1 : 0);
        int b1 = (c1 > 0.f) ? 1 : ((c1 < 0.f) ? -1 : 0);
        int b2 = (c2 > 0.f) ? 1 : ((c2 < 0.f) ? -1 : 0);
        int b3 = (c3 > 0.f) ? 1 : ((c3 < 0.f) ? -1 : 0);
        uint32_t p = (uint32_t)(b0 & 255) | ((uint32_t)(b1 & 255) << 8) |
                     ((uint32_t)(b2 & 255) << 16) | ((uint32_t)(b3 & 255) << 24);
        *reinterpret_cast<uint32_t*>(wrow + (size_t)(i * 256 + tid) * 4) = p;
    }
}

// ---------------- kernel 3: TMA-pipelined int8 mma.sync GEMM + per-group rescale ----------------
__global__ void __launch_bounds__(256, 1)
bitlinear_gemm(const __grid_constant__ CUtensorMap mapA,
               const __grid_constant__ CUtensorMap mapB,
               float* __restrict__ out) {
    extern __shared__ char smem[];
    const uint32_t sb = smem_u32(smem);
    const int tid = threadIdx.x;
    const int l = tid & 31;
    const int w = tid >> 5;
    const int wm = w & 3;       // 4 warps along M (32 rows each)
    const int wn = w >> 2;      // 2 warps along N (64 cols each)
    const int n0 = blockIdx.x * BN;
    const int m0 = blockIdx.y * BM;

    if (tid < 128)
        reinterpret_cast<float*>(smem + SM_ALPHA)[tid] = g_alpha[n0 + tid];
    if (tid == 0) {
#pragma unroll
        for (int s = 0; s < NSTAGE; s++) mbar_init(sb + SM_BARS + 8 * s, 1);
    }
    __syncthreads();

    // prologue: fill NSTAGE-1 stages
    if (tid == 0) {
#pragma unroll
        for (int kt = 0; kt < NSTAGE - 1; kt++) {
            mbar_expect(sb + SM_BARS + 8 * kt, STG_BYTES);
            uint32_t dst = sb + SM_TILE + kt * STG_BYTES;
            tma_load_2d(dst,           &mapA, kt * BK, m0, sb + SM_BARS + 8 * kt);
            tma_load_2d(dst + A_BYTES, &mapB, kt * BK, n0, sb + SM_BARS + 8 * kt);
        }
    }

    // ldmatrix address precompute: rows of 128 bytes, SW128 XOR = (row&7)<<4
    uint32_t aOff[2], aXor[2];
#pragma unroll
    for (int mi = 0; mi < 2; mi++) {
        int r = wm * 32 + mi * 16 + (l & 15);
        aOff[mi] = (uint32_t)r * 128u;
        aXor[mi] = (uint32_t)(r & 7) << 4;
    }
    const uint32_t akb = (uint32_t)(l >> 4) * 16u;   // byte-half of 32B k-slab
    const int g = l >> 3;
    uint32_t bOff[4], bXor[4];
#pragma unroll
    for (int nj4 = 0; nj4 < 4; nj4++) {
        int r = wn * 64 + nj4 * 16 + ((g >> 1) << 3) + (l & 7);
        bOff[nj4] = (uint32_t)r * 128u;
        bXor[nj4] = (uint32_t)(r & 7) << 4;
    }
    const uint32_t bkb = (uint32_t)(g & 1) * 16u;

    float facc[2][8][4];
#pragma unroll
    for (int mi = 0; mi < 2; mi++)
#pragma unroll
        for (int nj = 0; nj < 8; nj++)
#pragma unroll
            for (int c = 0; c < 4; c++) facc[mi][nj][c] = 0.f;

    // per-thread scale row base: rows m0 + wm*32 + (l>>2) + {0,8,16,24}
    const float* xsp = g_xs + (size_t)(m0 + wm * 32 + (l >> 2)) * NGRP;

    for (int kt = 0; kt < KITER; kt++) {
        const int s = kt & (NSTAGE - 1);
        // prefetch scales for the 2 groups of this kt: [g2][mi][rowhalf]
        float2 sg[2][2];
#pragma unroll
        for (int mi = 0; mi < 2; mi++)
#pragma unroll
            for (int h = 0; h < 2; h++)
                sg[mi][h] = *reinterpret_cast<const float2*>(
                    xsp + (size_t)(mi * 16 + h * 8) * NGRP + kt * 2);

        // refill the stage freed by iteration kt-1
        const int nk = kt + NSTAGE - 1;
        if (tid == 0 && nk < KITER) {
            const int sn = nk & (NSTAGE - 1);
            mbar_expect(sb + SM_BARS + 8 * sn, STG_BYTES);
            uint32_t dst = sb + SM_TILE + sn * STG_BYTES;
            tma_load_2d(dst,           &mapA, nk * BK, m0, sb + SM_BARS + 8 * sn);
            tma_load_2d(dst + A_BYTES, &mapB, nk * BK, n0, sb + SM_BARS + 8 * sn);
        }
        mbar_wait(sb + SM_BARS + 8 * s, (uint32_t)(kt >> 2) & 1u);
        const uint32_t ab = sb + SM_TILE + s * STG_BYTES;
        const uint32_t bb = ab + A_BYTES;

#pragma unroll
        for (int g2 = 0; g2 < 2; g2++) {           // two 64-K groups per kt
            int iacc[2][8][4];
#pragma unroll
            for (int ks2 = 0; ks2 < 2; ks2++) {    // two k32 steps per group
                const uint32_t ko = (uint32_t)(g2 * 2 + ks2) * 32u;
                uint32_t af[2][4], bf[4][4];
#pragma unroll
                for (int mi = 0; mi < 2; mi++)
                    ldsm_x4(ab + aOff[mi] + ((ko + akb) ^ aXor[mi]), af[mi]);
#pragma unroll
                for (int nj4 = 0; nj4 < 4; nj4++)
                    ldsm_x4(bb + bOff[nj4] + ((ko + bkb) ^ bXor[nj4]), bf[nj4]);
#pragma unroll
                for (int mi = 0; mi < 2; mi++)
#pragma unroll
                    for (int nj4 = 0; nj4 < 4; nj4++) {
                        if (ks2 == 0) {
                            imma_zero(iacc[mi][2 * nj4 + 0], af[mi], &bf[nj4][0]);
                            imma_zero(iacc[mi][2 * nj4 + 1], af[mi], &bf[nj4][2]);
                        } else {
                            imma_acc(iacc[mi][2 * nj4 + 0], af[mi], &bf[nj4][0]);
                            imma_acc(iacc[mi][2 * nj4 + 1], af[mi], &bf[nj4][2]);
                        }
                    }
            }
            // rescale this group's int sums into fp32 accumulators
#pragma unroll
            for (int mi = 0; mi < 2; mi++) {
                const float s0 = (g2 == 0) ? sg[mi][0].x : sg[mi][0].y;
                const float s1 = (g2 == 0) ? sg[mi][1].x : sg[mi][1].y;
#pragma unroll
                for (int nj = 0; nj < 8; nj++) {
                    facc[mi][nj][0] += (float)iacc[mi][nj][0] * s0;
                    facc[mi][nj][1] += (float)iacc[mi][nj][1] * s0;
                    facc[mi][nj][2] += (float)iacc[mi][nj][2] * s1;
                    facc[mi][nj][3] += (float)iacc[mi][nj][3] * s1;
                }
            }
        }
        __syncthreads();   // stage s free for refill at iteration kt+1
    }

    // ---- epilogue: scale by alpha[n], store fp32 ----
    const float* al = reinterpret_cast<const float*>(smem + SM_ALPHA);
    const int q = l >> 2, t4 = l & 3;
#pragma unroll
    for (int mi = 0; mi < 2; mi++) {
#pragma unroll
        for (int nj = 0; nj < 8; nj++) {
            const int nloc = wn * 64 + nj * 8 + t4 * 2;
            const float a0 = al[nloc], a1 = al[nloc + 1];
            const size_t r0 = (size_t)(m0 + wm * 32 + mi * 16 + q) * NN + n0 + nloc;
            float2 v0, v1;
            v0.x = facc[mi][nj][0] * a0; v0.y = facc[mi][nj][1] * a1;
            v1.x = facc[mi][nj][2] * a0; v1.y = facc[mi][nj][3] * a1;
            *reinterpret_cast<float2*>(out + r0) = v0;
            *reinterpret_cast<float2*>(out + r0 + 8 * NN) = v1;
        }
    }
}

// ---------------- host launch ----------------
typedef CUresult (*PFN_tmEncode)(CUtensorMap*, CUtensorMapDataType, cuuint32_t, void*,
                                 const cuuint64_t*, const cuuint64_t*, const cuuint32_t*,
                                 const cuuint32_t*, CUtensorMapInterleave, CUtensorMapSwizzle,
                                 CUtensorMapL2promotion, CUtensorMapFloatOOBfill);

extern "C" void kernel_launch(void* const* d_in, const int* in_sizes, int n_in,
                              void* d_out, int out_size) {
    (void)in_sizes; (void)n_in; (void)out_size;
    const float* x = (const float*)d_in[0];
    const float* W = (const float*)d_in[1];
    float* out = (float*)d_out;

    void* xa_ptr = nullptr;
    void* wb_ptr = nullptr;
    cudaGetSymbolAddress(&xa_ptr, g_xa);
    cudaGetSymbolAddress(&wb_ptr, g_wb);

    quant_x_kernel<<<32768, 256>>>(x);
    quant_w_kernel<<<NN, 256>>>(W);

    PFN_tmEncode enc = nullptr;
    cudaDriverEntryPointQueryResult qr;
    cudaGetDriverEntryPointByVersion("cuTensorMapEncodeTiled", (void**)&enc, 12000,
                                     cudaEnableDefault, &qr);
    CUtensorMap mapA, mapB;
    {
        cuuint64_t dims[2] = {(cuuint64_t)KK, (cuuint64_t)MM};
        cuuint64_t strd[1] = {(cuuint64_t)KK};
        cuuint32_t box[2]  = {BK, BM};
        cuuint32_t es[2]   = {1, 1};
        enc(&mapA, CU_TENSOR_MAP_DATA_TYPE_UINT8, 2, xa_ptr, dims, strd, box, es,
            CU_TENSOR_MAP_INTERLEAVE_NONE, CU_TENSOR_MAP_SWIZZLE_128B,
            CU_TENSOR_MAP_L2_PROMOTION_L2_128B, CU_TENSOR_MAP_FLOAT_OOB_FILL_NONE);
    }
    {
        cuuint64_t dims[2] = {(cuuint64_t)KK, (cuuint64_t)NN};
        cuuint64_t strd[1] = {(cuuint64_t)KK};
        cuuint32_t box[2]  = {BK, BN};
        cuuint32_t es[2]   = {1, 1};
        enc(&mapB, CU_TENSOR_MAP_DATA_TYPE_UINT8, 2, wb_ptr, dims, strd, box, es,
            CU_TENSOR_MAP_INTERLEAVE_NONE, CU_TENSOR_MAP_SWIZZLE_128B,
            CU_TENSOR_MAP_L2_PROMOTION_L2_128B, CU_TENSOR_MAP_FLOAT_OOB_FILL_NONE);
    }

    cudaFuncSetAttribute(bitlinear_gemm, cudaFuncAttributeMaxDynamicSharedMemorySize, SMEM_TOTAL);
    bitlinear_gemm<<<dim3(NN / BN, MM / BM), 256, SMEM_TOTAL>>>(mapA, mapB, out);
}

// round 4
// speedup vs baseline: 3.4563x; 3.4563x over previous
#include <cuda.h>
#include <cuda_runtime.h>
#include <cuda_fp16.h>
#include <cstdint>

// ---------------- problem sizes ----------------
#define MM 8192
#define NN 4096
#define KK 4096
#define GRP 64

#define BM 128
#define BN 128
#define BK 64
#define NSTAGE 3
#define KITER (KK / BK)          // 64

#define A_BYTES (BM * BK * 2)    // 16384
#define B_BYTES (BN * BK * 2)    // 16384
#define STG_BYTES (A_BYTES + B_BYTES)   // 32768

#define SM_ALPHA 0               /* 128 floats */
#define SM_BARS 512              /* NSTAGE mbarriers, 8B each */
#define SM_TILE 1024
#define SMEM_TOTAL (SM_TILE + NSTAGE * STG_BYTES)   /* 99328 -> 2 CTAs/SM */

// ---------------- scratch (no allocations allowed) ----------------
__device__ __align__(1024) __half g_xq[(size_t)MM * KK];   // 64 MB
__device__ __align__(1024) __half g_ws[(size_t)NN * KK];   // 32 MB
__device__ float g_alpha[NN];

// ---------------- PTX helpers (plain sm_90-level features only) ----------------
__device__ __forceinline__ uint32_t smem_u32(const void* p) {
    uint32_t a;
    asm("{ .reg .u64 t; cvta.to.shared.u64 t, %1; cvt.u32.u64 %0, t; }" : "=r"(a) : "l"(p));
    return a;
}
__device__ __forceinline__ void mbar_init(uint32_t a, uint32_t c) {
    asm volatile("mbarrier.init.shared.b64 [%0], %1;" :: "r"(a), "r"(c) : "memory");
}
__device__ __forceinline__ void mbar_expect(uint32_t a, uint32_t bytes) {
    asm volatile("mbarrier.arrive.expect_tx.shared.b64 _, [%0], %1;" :: "r"(a), "r"(bytes) : "memory");
}
__device__ __forceinline__ void mbar_wait(uint32_t a, uint32_t p) {
    asm volatile(
        "{\n\t.reg .pred P;\n\t"
        "WL%=:\n\t"
        "mbarrier.try_wait.parity.acquire.cta.shared::cta.b64 P, [%0], %1, 0x989680;\n\t"
        "@P bra.uni WD%=;\n\t"
        "bra.uni WL%=;\n\t"
        "WD%=:\n\t}"
        :: "r"(a), "r"(p) : "memory");
}
__device__ __forceinline__ void tma_load_2d(uint32_t smem_addr, const void* map,
                                            int cx, int cy, uint32_t mbar) {
    asm volatile(
        "cp.async.bulk.tensor.2d.shared::cta.global.tile.mbarrier::complete_tx::bytes "
        "[%0], [%1, {%2, %3}], [%4];"
        :: "r"(smem_addr), "l"(map), "r"(cx), "r"(cy), "r"(mbar) : "memory");
}
__device__ __forceinline__ void ldsm_x4(uint32_t addr, uint32_t* r) {
    asm volatile("ldmatrix.sync.aligned.m8n8.x4.shared.b16 {%0,%1,%2,%3}, [%4];"
                 : "=r"(r[0]), "=r"(r[1]), "=r"(r[2]), "=r"(r[3]) : "r"(addr));
}
__device__ __forceinline__ void mma16816(float* c, const uint32_t* a, const uint32_t* b) {
    asm volatile(
        "mma.sync.aligned.m16n8k16.row.col.f32.f16.f16.f32 "
        "{%0,%1,%2,%3}, {%4,%5,%6,%7}, {%8,%9}, {%0,%1,%2,%3};"
        : "+f"(c[0]), "+f"(c[1]), "+f"(c[2]), "+f"(c[3])
        : "r"(a[0]), "r"(a[1]), "r"(a[2]), "r"(a[3]), "r"(b[0]), "r"(b[1]));
}

// ---------------- kernel 1: group-64 absmax fake-quant of x -> fp16 ----------------
__global__ void __launch_bounds__(256) quant_x_kernel(const float* __restrict__ x) {
    uint32_t t = blockIdx.x * 256u + threadIdx.x;
    size_t base = (size_t)(t >> 4) * GRP + (size_t)(t & 15) * 4;
    float4 v = *reinterpret_cast<const float4*>(x + base);
    float am = fmaxf(fmaxf(fabsf(v.x), fabsf(v.y)), fmaxf(fabsf(v.z), fabsf(v.w)));
    am = fmaxf(am, __shfl_xor_sync(0xFFFFFFFFu, am, 1));
    am = fmaxf(am, __shfl_xor_sync(0xFFFFFFFFu, am, 2));
    am = fmaxf(am, __shfl_xor_sync(0xFFFFFFFFu, am, 4));
    am = fmaxf(am, __shfl_xor_sync(0xFFFFFFFFu, am, 8));
    float s = fmaxf(am, 1e-8f);
    float inv = __fdividef(127.0f, s);
    float sc = s * (1.0f / 127.0f);
    // q = clip(round(x/s*127)); xq = q*s/127
    float q0 = fminf(fmaxf(rintf(v.x * inv), -127.f), 127.f);
    float q1 = fminf(fmaxf(rintf(v.y * inv), -127.f), 127.f);
    float q2 = fminf(fmaxf(rintf(v.z * inv), -127.f), 127.f);
    float q3 = fminf(fmaxf(rintf(v.w * inv), -127.f), 127.f);
    __half2 h0 = __floats2half2_rn(q0 * sc, q1 * sc);
    __half2 h1 = __floats2half2_rn(q2 * sc, q3 * sc);
    uint2 u;
    u.x = *reinterpret_cast<uint32_t*>(&h0);
    u.y = *reinterpret_cast<uint32_t*>(&h1);
    *reinterpret_cast<uint2*>(g_xq + base) = u;
}

// ---------------- kernel 2: per-row W binarize (centered sign) + alpha ----------------
__device__ __forceinline__ float sgnf(float c) { return (c > 0.f) ? 1.f : ((c < 0.f) ? -1.f : 0.f); }

__global__ void __launch_bounds__(256) quant_w_kernel(const float* __restrict__ W) {
    const int row = blockIdx.x;
    const int tid = threadIdx.x;
    const float4* wr = reinterpret_cast<const float4*>(W + (size_t)row * KK);
    float4 v[4];
    float s = 0.f;
#pragma unroll
    for (int i = 0; i < 4; i++) {
        v[i] = wr[i * 256 + tid];
        s += (v[i].x + v[i].y) + (v[i].z + v[i].w);
    }
    __shared__ float red[256];
    red[tid] = s;
    __syncthreads();
#pragma unroll
    for (int o = 128; o > 0; o >>= 1) {
        if (tid < o) red[tid] += red[tid + o];
        __syncthreads();
    }
    float mean = red[0] * (1.0f / 4096.0f);
    __syncthreads();
    float sa = 0.f;
#pragma unroll
    for (int i = 0; i < 4; i++)
        sa += (fabsf(v[i].x - mean) + fabsf(v[i].y - mean)) +
              (fabsf(v[i].z - mean) + fabsf(v[i].w - mean));
    red[tid] = sa;
    __syncthreads();
#pragma unroll
    for (int o = 128; o > 0; o >>= 1) {
        if (tid < o) red[tid] += red[tid + o];
        __syncthreads();
    }
    if (tid == 0) g_alpha[row] = red[0] * (1.0f / 4096.0f);
    __half* wrow = g_ws + (size_t)row * KK;
#pragma unroll
    for (int i = 0; i < 4; i++) {
        __half2 h0 = __floats2half2_rn(sgnf(v[i].x - mean), sgnf(v[i].y - mean));
        __half2 h1 = __floats2half2_rn(sgnf(v[i].z - mean), sgnf(v[i].w - mean));
        uint2 u;
        u.x = *reinterpret_cast<uint32_t*>(&h0);
        u.y = *reinterpret_cast<uint32_t*>(&h1);
        *reinterpret_cast<uint2*>(wrow + (size_t)(i * 256 + tid) * 4) = u;
    }
}

// ---------------- kernel 3: TMA-pipelined mma.sync f16 GEMM (BM=BN=128, BK=64) ----------------
__global__ void __launch_bounds__(256, 2)
bitlinear_gemm(const __grid_constant__ CUtensorMap mapA,
               const __grid_constant__ CUtensorMap mapB,
               float* __restrict__ out) {
    extern __shared__ char smem[];
    const uint32_t sb = smem_u32(smem);
    const int tid = threadIdx.x;
    const int l = tid & 31;
    const int w = tid >> 5;
    const int wm = w & 3;       // 4 warps along M (32 rows each)
    const int wn = w >> 2;      // 2 warps along N (64 cols each)
    const int n0 = blockIdx.x * BN;
    const int m0 = blockIdx.y * BM;

    if (tid < 128)
        reinterpret_cast<float*>(smem + SM_ALPHA)[tid] = g_alpha[n0 + tid];
    if (tid == 0) {
#pragma unroll
        for (int s = 0; s < NSTAGE; s++) mbar_init(sb + SM_BARS + 8 * s, 1);
    }
    __syncthreads();

    // prologue: fill NSTAGE-1 stages
    if (tid == 0) {
#pragma unroll
        for (int kt = 0; kt < NSTAGE - 1; kt++) {
            mbar_expect(sb + SM_BARS + 8 * kt, STG_BYTES);
            uint32_t dst = sb + SM_TILE + kt * STG_BYTES;
            tma_load_2d(dst,           &mapA, kt * BK, m0, sb + SM_BARS + 8 * kt);
            tma_load_2d(dst + A_BYTES, &mapB, kt * BK, n0, sb + SM_BARS + 8 * kt);
        }
    }

    // per-thread ldmatrix address precompute (SW128 swizzle XOR = (row&7)<<4)
    uint32_t aRow[2], aXor[2];
#pragma unroll
    for (int mi = 0; mi < 2; mi++) {
        int r = wm * 32 + mi * 16 + (l & 15);
        aRow[mi] = (uint32_t)r * 128u;
        aXor[mi] = (uint32_t)(r & 7) << 4;
    }
    const uint32_t akb = (uint32_t)(l >> 4) * 16u;
    const int g = l >> 3;
    uint32_t bRow[4], bXor[4];
#pragma unroll
    for (int nj4 = 0; nj4 < 4; nj4++) {
        int r = wn * 64 + nj4 * 16 + ((g >> 1) << 3) + (l & 7);
        bRow[nj4] = (uint32_t)r * 128u;
        bXor[nj4] = (uint32_t)(r & 7) << 4;
    }
    const uint32_t bkb = (uint32_t)(g & 1) * 16u;

    float acc[2][8][4];
#pragma unroll
    for (int mi = 0; mi < 2; mi++)
#pragma unroll
        for (int nj = 0; nj < 8; nj++)
#pragma unroll
            for (int c = 0; c < 4; c++) acc[mi][nj][c] = 0.f;

    int stage = 0, phase = 0;
    for (int kt = 0; kt < KITER; kt++) {
        // refill the stage freed by iteration kt-1 (freed by its trailing syncthreads)
        const int nk = kt + NSTAGE - 1;
        if (tid == 0 && nk < KITER) {
            int sn = stage + NSTAGE - 1; if (sn >= NSTAGE) sn -= NSTAGE;
            mbar_expect(sb + SM_BARS + 8 * sn, STG_BYTES);
            uint32_t dst = sb + SM_TILE + sn * STG_BYTES;
            tma_load_2d(dst,           &mapA, nk * BK, m0, sb + SM_BARS + 8 * sn);
            tma_load_2d(dst + A_BYTES, &mapB, nk * BK, n0, sb + SM_BARS + 8 * sn);
        }
        mbar_wait(sb + SM_BARS + 8 * stage, (uint32_t)phase);
        const uint32_t ab = sb + SM_TILE + stage * STG_BYTES;
        const uint32_t bb = ab + A_BYTES;
#pragma unroll
        for (int ks = 0; ks < BK / 16; ks++) {
            uint32_t af[2][4], bf[4][4];
#pragma unroll
            for (int mi = 0; mi < 2; mi++)
                ldsm_x4(ab + aRow[mi] + (((uint32_t)ks * 32u + akb) ^ aXor[mi]), af[mi]);
#pragma unroll
            for (int nj4 = 0; nj4 < 4; nj4++)
                ldsm_x4(bb + bRow[nj4] + (((uint32_t)ks * 32u + bkb) ^ bXor[nj4]), bf[nj4]);
#pragma unroll
            for (int mi = 0; mi < 2; mi++)
#pragma unroll
                for (int nj4 = 0; nj4 < 4; nj4++) {
                    mma16816(acc[mi][2 * nj4 + 0], af[mi], &bf[nj4][0]);
                    mma16816(acc[mi][2 * nj4 + 1], af[mi], &bf[nj4][2]);
                }
        }
        __syncthreads();   // stage free for refill at iteration kt+1
        if (++stage == NSTAGE) { stage = 0; phase ^= 1; }
    }

    // ---- epilogue: scale by alpha[n], store fp32 ----
    const float* al = reinterpret_cast<const float*>(smem + SM_ALPHA);
    const int q = l >> 2, t4 = l & 3;
#pragma unroll
    for (int mi = 0; mi < 2; mi++) {
#pragma unroll
        for (int nj = 0; nj < 8; nj++) {
            const int nloc = wn * 64 + nj * 8 + t4 * 2;
            const float a0 = al[nloc], a1 = al[nloc + 1];
            const size_t r0 = (size_t)(m0 + wm * 32 + mi * 16 + q) * NN + n0 + nloc;
            float2 v0, v1;
            v0.x = acc[mi][nj][0] * a0; v0.y = acc[mi][nj][1] * a1;
            v1.x = acc[mi][nj][2] * a0; v1.y = acc[mi][nj][3] * a1;
            *reinterpret_cast<float2*>(out + r0) = v0;
            *reinterpret_cast<float2*>(out + r0 + 8 * NN) = v1;
        }
    }
}

// ---------------- host launch ----------------
typedef CUresult (*PFN_tmEncode)(CUtensorMap*, CUtensorMapDataType, cuuint32_t, void*,
                                 const cuuint64_t*, const cuuint64_t*, const cuuint32_t*,
                                 const cuuint32_t*, CUtensorMapInterleave, CUtensorMapSwizzle,
                                 CUtensorMapL2promotion, CUtensorMapFloatOOBfill);

extern "C" void kernel_launch(void* const* d_in, const int* in_sizes, int n_in,
                              void* d_out, int out_size) {
    (void)in_sizes; (void)n_in; (void)out_size;
    const float* x = (const float*)d_in[0];
    const float* W = (const float*)d_in[1];
    float* out = (float*)d_out;

    void* xq_ptr = nullptr;
    void* ws_ptr = nullptr;
    cudaGetSymbolAddress(&xq_ptr, g_xq);
    cudaGetSymbolAddress(&ws_ptr, g_ws);

    quant_x_kernel<<<32768, 256>>>(x);
    quant_w_kernel<<<NN, 256>>>(W);

    PFN_tmEncode enc = nullptr;
    cudaDriverEntryPointQueryResult qr;
    cudaGetDriverEntryPointByVersion("cuTensorMapEncodeTiled", (void**)&enc, 12000,
                                     cudaEnableDefault, &qr);
    CUtensorMap mapA, mapB;
    {
        cuuint64_t dims[2] = {(cuuint64_t)KK, (cuuint64_t)MM};
        cuuint64_t strd[1] = {(cuuint64_t)KK * 2};
        cuuint32_t box[2]  = {BK, BM};
        cuuint32_t es[2]   = {1, 1};
        enc(&mapA, CU_TENSOR_MAP_DATA_TYPE_FLOAT16, 2, xq_ptr, dims, strd, box, es,
            CU_TENSOR_MAP_INTERLEAVE_NONE, CU_TENSOR_MAP_SWIZZLE_128B,
            CU_TENSOR_MAP_L2_PROMOTION_L2_128B, CU_TENSOR_MAP_FLOAT_OOB_FILL_NONE);
    }
    {
        cuuint64_t dims[2] = {(cuuint64_t)KK, (cuuint64_t)NN};
        cuuint64_t strd[1] = {(cuuint64_t)KK * 2};
        cuuint32_t box[2]  = {BK, BN};
        cuuint32_t es[2]   = {1, 1};
        enc(&mapB, CU_TENSOR_MAP_DATA_TYPE_FLOAT16, 2, ws_ptr, dims, strd, box, es,
            CU_TENSOR_MAP_INTERLEAVE_NONE, CU_TENSOR_MAP_SWIZZLE_128B,
            CU_TENSOR_MAP_L2_PROMOTION_L2_128B, CU_TENSOR_MAP_FLOAT_OOB_FILL_NONE);
    }

    cudaFuncSetAttribute(bitlinear_gemm, cudaFuncAttributeMaxDynamicSharedMemorySize, SMEM_TOTAL);
    bitlinear_gemm<<<dim3(NN / BN, MM / BM), 256, SMEM_TOTAL>>>(mapA, mapB, out);
}